// round 16
// baseline (speedup 1.0000x reference)
#include <cuda_runtime.h>
#include <cuda_fp16.h>
#include <cstdint>
#include <math.h>

typedef __half fp16;

// Problem constants
#define BB 4
#define TT 512
#define DD 1024
#define HH 8
#define DH 64
#define HD 512
#define PP 2048
#define NTOK (BB*TT)          // 2048 tokens

// ================= scratch (device globals) =================================
__device__ fp16  g_xn16[NTOK*DD];
__device__ float g_xt  [NTOK*PP];
__device__ fp16  g_xt16[NTOK*PP];
__device__ fp16  g_xc16[NTOK*PP];
__device__ float g_r   [NTOK*HD], g_skip[NTOK*HD];
__device__ float g_q   [NTOK*HD], g_k   [NTOK*HD];
__device__ float g_v   [NTOK*HD], g_o   [NTOK*HD];
__device__ float g_ig  [NTOK*HH], g_fg  [NTOK*HH];
__device__ float g_a   [BB*HH*TT], g_M [BB*HH*TT];
__device__ fp16  g_cm16[NTOK*HD];
// transposed weights (fp16): WT[N,K]
__device__ fp16 g_WlrT[2560*DD];      // [Wl | Wr] cols, K=1024
__device__ fp16 g_WsT[HD*PP], g_WqT[HD*PP], g_WkT[HD*PP];
__device__ fp16 g_WvT[HD*PP], g_WoT[HD*PP], g_WdT[DD*HD];
__device__ float g_bias_lr[2560];
__device__ float g_WiT[HH*PP], g_WfT[HH*PP];   // gate weights transposed [H][P]

__device__ __forceinline__ uint32_t smem_u32(const void* p) {
    uint32_t a;
    asm("{ .reg .u64 t; cvta.to.shared.u64 t, %1; cvt.u32.u64 %0, t; }"
        : "=r"(a) : "l"(p));
    return a;
}
__device__ __forceinline__ void cp16(uint32_t s, const void* g) {
    asm volatile("cp.async.cg.shared.global [%0], [%1], 16;" :: "r"(s), "l"(g));
}
__device__ __forceinline__ void ldm4(uint32_t addr, uint32_t* r) {
    asm volatile("ldmatrix.sync.aligned.m8n8.x4.shared.b16 {%0,%1,%2,%3}, [%4];"
                 : "=r"(r[0]), "=r"(r[1]), "=r"(r[2]), "=r"(r[3]) : "r"(addr));
}
__device__ __forceinline__ void mma16816(float* c, const uint32_t* a,
                                         uint32_t b0, uint32_t b1) {
    asm volatile("mma.sync.aligned.m16n8k16.row.col.f32.f16.f16.f32 "
        "{%0,%1,%2,%3}, {%4,%5,%6,%7}, {%8,%9}, {%0,%1,%2,%3};"
        : "+f"(c[0]), "+f"(c[1]), "+f"(c[2]), "+f"(c[3])
        : "r"(a[0]), "r"(a[1]), "r"(a[2]), "r"(a[3]), "r"(b0), "r"(b1));
}

// ============ fused preprocessing: 8 weight transposes + misc + LN =========
struct FusedPrep {
    const float* W[8];
    fp16* T[8];
    int K[8], N[8], cum[9];
    const float *bl, *br, *Wi, *Wf;
    const float *x, *lnw, *lnb;
    fp16* xn16;
    int miscEnd;                       // cum[8] + 74
};
__global__ __launch_bounds__(256) void fused_prep_kernel(FusedPrep fp)
{
    __shared__ float shmem[32 * 33];
    const int bx = blockIdx.x, tid = threadIdx.x;

    if (bx < fp.cum[8]) {
        int j = 0;
        #pragma unroll
        for (int i = 0; i < 8; i++) if (bx >= fp.cum[i + 1]) j = i + 1;
        const int local = bx - fp.cum[j];
        const int K = fp.K[j], N = fp.N[j];
        const int nbn = N / 32;
        const int n0 = (local % nbn) * 32, k0 = (local / nbn) * 32;
        const float* W = fp.W[j];
        fp16* T = fp.T[j];
        float (*tile)[33] = (float(*)[33])shmem;
        int tx = tid & 31, ty = tid >> 5;
        for (int r = ty; r < 32; r += 8)
            tile[r][tx] = W[(size_t)(k0 + r) * N + n0 + tx];
        __syncthreads();
        for (int r = ty; r < 32; r += 8)
            T[(size_t)(n0 + r) * K + k0 + tx] = __float2half(tile[tx][r]);
    } else if (bx < fp.miscEnd) {
        const int blk = bx - fp.cum[8];
        if (blk < 10) {
            int idx = blk * 256 + tid;
            if (idx < 2560)
                g_bias_lr[idx] = (idx < PP) ? fp.bl[idx] : fp.br[idx - PP];
        } else {
            int idx = (blk - 10) * 256 + tid;   // 0..16383 over [8][2048]
            int h = idx >> 11, p = idx & 2047;
            g_WiT[idx] = fp.Wi[p * HH + h];
            g_WfT[idx] = fp.Wf[p * HH + h];
        }
    } else {
        const int t = bx - fp.miscEnd;
        const float* row = fp.x + (size_t)t * DD;
        float s = 0.f, s2 = 0.f;
        for (int i = tid; i < DD; i += 256) {
            float v = row[i]; s += v; s2 += v * v;
        }
        int warp = tid >> 5, lane = tid & 31;
        #pragma unroll
        for (int o = 16; o; o >>= 1) {
            s  += __shfl_xor_sync(0xffffffffu, s,  o);
            s2 += __shfl_xor_sync(0xffffffffu, s2, o);
        }
        if (lane == 0) { shmem[warp] = s; shmem[8 + warp] = s2; }
        __syncthreads();
        if (tid == 0) {
            float ts = 0.f, ts2 = 0.f;
            #pragma unroll
            for (int i = 0; i < 8; i++) { ts += shmem[i]; ts2 += shmem[8 + i]; }
            float mu  = ts  * (1.f / DD);
            float var = ts2 * (1.f / DD) - mu * mu;
            shmem[0] = mu; shmem[1] = rsqrtf(var + 1e-6f);
        }
        __syncthreads();
        float mu = shmem[0], rstd = shmem[1];
        for (int i = tid; i < DD; i += 256)
            fp.xn16[(size_t)t * DD + i] =
                __float2half((row[i] - mu) * rstd * fp.lnw[i] + fp.lnb[i]);
    }
}

// ============ mma.sync fp16 single-pass GEMM (BK=32, 4-stage) ==============
// blockIdx.z == scanz runs the gate prefix-scan instead (concurrent w/ GEMM).
struct GemmJob {
    const fp16 *A, *B;
    const float *bias, *res;
    float *out;
    fp16 *o16;
    float *out2;                  // columns >= ncut go here (ld = ldo2)
    int ncut, ldo, ldo2;
};
struct GemmParams {
    GemmJob jobs[6]; int K;
    int scanz;
    const float *gi, *gf;
    float *aex, *Mex;
};

#define PADK 40                        // halves per smem row (32 + 8 pad)
#define OPT  (128*PADK)                // halves per operand tile
#define STG2 (2*OPT)                   // halves per stage (A, B)
#define NSTG 4
#define GSMEM_BYTES (NSTG*STG2*2)      // 81920 B -> 2 CTAs/SM

__global__ __launch_bounds__(256, 2) void gemm_mma_kernel(GemmParams p)
{
    extern __shared__ fp16 smg[];

    if ((int)blockIdx.z == p.scanz) {
        // ---------- gate prefix scans (exact linearization), 256 threads ----
        const int cta = blockIdx.y * gridDim.x + blockIdx.x;
        if (cta >= BB * HH) return;
        const int b = cta >> 3, h = cta & 7;
        const int tid = threadIdx.x;
        const int p1 = tid + 256;
        float* sf = (float*)smg;         // [512]
        float* sa = sf + TT;             // [512]
        const int g0 = (b * TT + tid) * HH + h;
        const int g1 = (b * TT + p1) * HH + h;
        sf[tid] = p.gf[g0];
        sf[p1]  = p.gf[g1];
        const float iv0 = p.gi[g0], iv1 = p.gi[g1];
        __syncthreads();
        #pragma unroll
        for (int st = 1; st < TT; st <<= 1) {
            float a0 = (tid >= st) ? sf[tid - st] : 0.f;
            float a1 = (p1  >= st) ? sf[p1  - st] : 0.f;
            __syncthreads();
            sf[tid] += a0; sf[p1] += a1;
            __syncthreads();
        }
        const float av0 = iv0 - sf[tid], av1 = iv1 - sf[p1];
        p.aex[cta * TT + tid] = av0;
        p.aex[cta * TT + p1]  = av1;
        sa[tid] = av0; sa[p1] = av1;
        __syncthreads();
        #pragma unroll
        for (int st = 1; st < TT; st <<= 1) {
            float m0 = (tid >= st) ? sa[tid - st] : -3.4e38f;
            float m1 = (p1  >= st) ? sa[p1  - st] : -3.4e38f;
            __syncthreads();
            sa[tid] = fmaxf(sa[tid], m0);
            sa[p1]  = fmaxf(sa[p1],  m1);
            __syncthreads();
        }
        p.Mex[cta * TT + tid] = fmaxf(0.f, sa[tid]);
        p.Mex[cta * TT + p1]  = fmaxf(0.f, sa[p1]);
        return;
    }

    const GemmJob J = p.jobs[blockIdx.z];
    const int bm = blockIdx.y * 128, bn = blockIdx.x * 128;
    const uint32_t sbase = smem_u32(smg);
    const int K = p.K;
    const int tid = threadIdx.x, lane = tid & 31, wid = tid >> 5;
    const int warpM = wid & 3, warpN = wid >> 2;    // 4 x 2 warps, tile 32x64

    const fp16* gsrc[2];
    gsrc[0] = J.A + (size_t)bm * K;
    gsrc[1] = J.B + (size_t)bn * K;

    const int lrow = tid >> 1;
    const int lcol = (tid & 1) * 16;   // halves
    const uint32_t swr = sbase + (uint32_t)(lrow * PADK + lcol) * 2;

    float acc[2][8][4];
    #pragma unroll
    for (int i = 0; i < 2; i++)
        #pragma unroll
        for (int j = 0; j < 8; j++)
            #pragma unroll
            for (int e = 0; e < 4; e++) acc[i][j][e] = 0.f;

    const int NT = K / 32;

    // preload stages 0..2
    #pragma unroll
    for (int s = 0; s < 3; s++) {
        #pragma unroll
        for (int w = 0; w < 2; w++) {
            const fp16* g = gsrc[w] + (size_t)lrow * K + s * 32 + lcol;
            uint32_t sa = swr + (uint32_t)(s * STG2 + w * OPT) * 2;
            cp16(sa, g); cp16(sa + 16, g + 8);
        }
        asm volatile("cp.async.commit_group;");
    }

    for (int kt = 0; kt < NT; kt++) {
        if (kt < NT - 2)      asm volatile("cp.async.wait_group 2;");
        else if (kt < NT - 1) asm volatile("cp.async.wait_group 1;");
        else                  asm volatile("cp.async.wait_group 0;");
        __syncthreads();

        if (kt + 3 < NT) {
            const int s = (kt + 3) % NSTG;
            const int k0 = (kt + 3) * 32;
            #pragma unroll
            for (int w = 0; w < 2; w++) {
                const fp16* g = gsrc[w] + (size_t)lrow * K + k0 + lcol;
                uint32_t sa = swr + (uint32_t)(s * STG2 + w * OPT) * 2;
                cp16(sa, g); cp16(sa + 16, g + 8);
            }
            asm volatile("cp.async.commit_group;");
        }

        const uint32_t stg = sbase + (uint32_t)((kt % NSTG) * STG2) * 2;
        #pragma unroll
        for (int ks = 0; ks < 2; ks++) {
            const int koff = ks * 16 + ((lane >> 4) << 3);
            const int rsel = lane & 15;
            uint32_t a[2][4], b[4][4];
            #pragma unroll
            for (int i = 0; i < 2; i++) {
                const int row = warpM * 32 + i * 16 + rsel;
                ldm4(stg + (uint32_t)(row * PADK + koff) * 2, a[i]);
            }
            #pragma unroll
            for (int j = 0; j < 4; j++) {
                const int row = warpN * 64 + j * 16 + rsel;
                ldm4(stg + (uint32_t)(OPT + row * PADK + koff) * 2, b[j]);
            }
            #pragma unroll
            for (int i = 0; i < 2; i++)
                #pragma unroll
                for (int j = 0; j < 8; j++)
                    mma16816(acc[i][j], a[i],
                             b[j >> 1][j & 1], b[j >> 1][(j & 1) + 2]);
        }
    }

    const int er = (lane >> 2);
    const int ec = (lane & 3) * 2;
    #pragma unroll
    for (int i = 0; i < 2; i++) {
        #pragma unroll
        for (int j = 0; j < 8; j++) {
            const int row0 = bm + warpM * 32 + i * 16 + er;
            const int col0 = bn + warpN * 64 + j * 8 + ec;
            #pragma unroll
            for (int e = 0; e < 4; e++) {
                const int row = row0 + (e >> 1) * 8;
                const int col = col0 + (e & 1);
                float v = acc[i][j][e] + J.bias[col];
                if (col >= J.ncut) {
                    J.out2[(size_t)row * J.ldo2 + (col - J.ncut)] = v;
                } else {
                    if (J.res) v += J.res[(size_t)row * J.ldo + col];
                    const size_t idx = (size_t)row * J.ldo + col;
                    J.out[idx] = v;
                    if (J.o16) J.o16[idx] = __float2half(v);
                }
            }
        }
    }
}

// ====== fused causal conv + silu + i/f gates (one CTA per token) ===========
__global__ __launch_bounds__(256) void conv_gates_kernel(
    const float* __restrict__ xt, const float* __restrict__ cw,
    const float* __restrict__ cbp, fp16* __restrict__ xc16,
    const float* __restrict__ WiT, const float* __restrict__ bi,
    const float* __restrict__ WfT, const float* __restrict__ bf_,
    float* __restrict__ gi, float* __restrict__ gf)
{
    const int t = blockIdx.x, tid = threadIdx.x;
    __shared__ float row[PP];
    __shared__ float y[PP];
    __shared__ float red[16];

    // load xt row
    {
        const float4* src = (const float4*)(xt + (size_t)t * PP);
        float4* rs = (float4*)row;
        rs[tid]       = src[tid];
        rs[tid + 256] = src[tid + 256];
    }
    __syncthreads();

    // conv + silu -> y (smem) + xc16 (gmem)
    const float w0 = cw[0], w1 = cw[1], w2 = cw[2], w3 = cw[3], cb = cbp[0];
    #pragma unroll
    for (int i = 0; i < 2; i++) {
        const int p = (tid + 256 * i) * 4;
        float o[4];
        #pragma unroll
        for (int e = 0; e < 4; e++) {
            const int pp = p + e;
            float acc = row[pp] * w3 + cb;
            if (pp >= 1) acc += row[pp - 1] * w2;
            if (pp >= 2) acc += row[pp - 2] * w1;
            if (pp >= 3) acc += row[pp - 3] * w0;
            o[e] = acc / (1.f + __expf(-acc));
        }
        *(float4*)&y[p] = make_float4(o[0], o[1], o[2], o[3]);
        __half2* h2 = (__half2*)(xc16 + (size_t)t * PP + p);
        h2[0] = __floats2half2_rn(o[0], o[1]);
        h2[1] = __floats2half2_rn(o[2], o[3]);
    }
    __syncthreads();

    // gates: warp w -> head w, dot over y (smem) with coalesced weights
    const int warp = tid >> 5, lane = tid & 31;
    const float* wi = WiT + warp * PP;
    const float* wf = WfT + warp * PP;
    float si = 0.f, sf = 0.f;
    for (int p = lane * 4; p < PP; p += 128) {
        float4 xv = *(const float4*)&y[p];
        float4 a  = *(const float4*)(wi + p);
        float4 b  = *(const float4*)(wf + p);
        si += xv.x*a.x + xv.y*a.y + xv.z*a.z + xv.w*a.w;
        sf += xv.x*b.x + xv.y*b.y + xv.z*b.z + xv.w*b.w;
    }
    #pragma unroll
    for (int o = 16; o; o >>= 1) {
        si += __shfl_xor_sync(0xffffffffu, si, o);
        sf += __shfl_xor_sync(0xffffffffu, sf, o);
    }
    if (lane == 0) {
        float a  = si + bi[warp];
        float b2 = sf + bf_[warp];
        gi[t * HH + warp] = 15.f * tanhf(a  * (1.f / 15.f));
        gf[t * HH + warp] = 15.f * tanhf(b2 * (1.f / 15.f));
    }
    (void)red;
}

// ================= parallel attention-form scan ============================
#define QT 64
#define AP 68                       // row pad (floats); 272B, 16B aligned
#define ASM_BYTES ((4*QT*AP + QT) * 4)

__global__ __launch_bounds__(256) void attn_kernel(
    const float* __restrict__ q, const float* __restrict__ kraw,
    const float* __restrict__ v, const float* __restrict__ aex,
    const float* __restrict__ Mex, const float* __restrict__ oraw,
    const float* __restrict__ skip, const float* __restrict__ rraw,
    const float* __restrict__ hlnw, const float* __restrict__ hlnb,
    fp16* __restrict__ out16)
{
    const int bh = blockIdx.y, b = bh >> 3, h = bh & 7;
    const int t0 = blockIdx.x * QT;
    extern __shared__ float sm[];
    float* ks = sm;                  // [64][AP]
    float* vs = ks + QT * AP;
    float* qs = vs + QT * AP;
    float* ss = qs + QT * AP;
    float* as_ = ss + QT * AP;       // [64]

    const int tid = threadIdx.x;
    const int qi = tid >> 2, sub = tid & 3;
    const int tq = t0 + qi;
    const size_t qbase = (size_t)(b * TT + tq) * HD + h * DH;

    {
        const int lr = tid >> 2, lc = (tid & 3) * 16;
        const float* src = q + (size_t)(b * TT + t0 + lr) * HD + h * DH + lc;
        #pragma unroll
        for (int i = 0; i < 16; i += 4)
            *(float4*)&qs[lr * AP + lc + i] = *(const float4*)(src + i);
    }
    __syncthreads();

    const float Mt = Mex[bh * TT + tq];
    float num[16];
    #pragma unroll
    for (int i = 0; i < 16; i++) num[i] = 0.f;
    float den = 0.f;

    for (int j0 = 0; j0 <= t0; j0 += QT) {
        {
            const int lr = tid >> 2, lc = (tid & 3) * 16;
            const size_t gb = (size_t)(b * TT + j0 + lr) * HD + h * DH + lc;
            #pragma unroll
            for (int i = 0; i < 16; i += 4) {
                *(float4*)&ks[lr * AP + lc + i] = *(const float4*)(kraw + gb + i);
                *(float4*)&vs[lr * AP + lc + i] = *(const float4*)(v + gb + i);
            }
            if (tid < QT) as_[tid] = aex[bh * TT + j0 + tid];
        }
        __syncthreads();

        float sc[16];
        #pragma unroll
        for (int jj = 0; jj < 16; jj++) sc[jj] = 0.f;
        const float* qrow = &qs[qi * AP];
        #pragma unroll 4
        for (int d = 0; d < DH; d += 4) {
            float q0 = qrow[d], q1 = qrow[d+1], q2 = qrow[d+2], q3 = qrow[d+3];
            #pragma unroll
            for (int jj = 0; jj < 16; jj++) {
                const float* kr = &ks[(sub + 4*jj) * AP + d];
                sc[jj] += q0*kr[0] + q1*kr[1] + q2*kr[2] + q3*kr[3];
            }
        }
        const bool diag = (j0 == t0);
        #pragma unroll
        for (int jj = 0; jj < 16; jj++) {
            const int j = sub + 4*jj;
            float w = (diag && j > qi) ? 0.f
                      : __expf(as_[j] - Mt) * 0.125f * sc[jj];
            ss[qi * AP + j] = w;
            den += w;
        }
        __syncthreads();

        #pragma unroll 8
        for (int j = 0; j < QT; j++) {
            const float s = ss[qi * AP + j];
            const float* vr = &vs[j * AP + sub];
            #pragma unroll
            for (int dd = 0; dd < 16; dd++)
                num[dd] += s * vr[4*dd];
        }
        __syncthreads();
    }

    float sumq = 0.f;
    #pragma unroll
    for (int dd = 0; dd < 16; dd++) sumq += qs[qi * AP + sub + 4*dd];
    den  += __shfl_xor_sync(0xffffffffu, den, 1);
    den  += __shfl_xor_sync(0xffffffffu, den, 2);
    sumq += __shfl_xor_sync(0xffffffffu, sumq, 1);
    sumq += __shfl_xor_sync(0xffffffffu, sumq, 2);
    den = fmaxf(den + __expf(-Mt) * sumq, 1.0f);
    const float rden = 1.f / den;

    float hh[16], s1 = 0.f, s2 = 0.f;
    #pragma unroll
    for (int dd = 0; dd < 16; dd++) {
        const int d = sub + 4*dd;
        const float ov = oraw[qbase + d];
        const float og = 1.f / (1.f + __expf(-ov));
        const float hv = og * num[dd] * rden;
        hh[dd] = hv;
        s1 += hv; s2 += hv * hv;
    }
    s1 += __shfl_xor_sync(0xffffffffu, s1, 1);
    s1 += __shfl_xor_sync(0xffffffffu, s1, 2);
    s2 += __shfl_xor_sync(0xffffffffu, s2, 1);
    s2 += __shfl_xor_sync(0xffffffffu, s2, 2);
    const float mu  = s1 * (1.f / DH);
    const float var = s2 * (1.f / DH) - mu * mu;
    const float rstd = rsqrtf(var + 1e-6f);
    #pragma unroll
    for (int dd = 0; dd < 16; dd++) {
        const int d = sub + 4*dd;
        const float hn = (hh[dd] - mu) * rstd * hlnw[h*DH + d] + hlnb[h*DH + d];
        const float rv = rraw[qbase + d];
        const float sil = rv / (1.f + __expf(-rv));
        out16[qbase + d] = __float2half((hn + skip[qbase + d]) * sil);
    }
}

// ===========================================================================
extern "C" void kernel_launch(void* const* d_in, const int* in_sizes, int n_in,
                              void* d_out, int out_size)
{
    const float* x      = (const float*)d_in[0];
    const float* ln_w   = (const float*)d_in[1];
    const float* ln_b   = (const float*)d_in[2];
    const float* hln_w  = (const float*)d_in[3];
    const float* hln_b  = (const float*)d_in[4];
    const float* Wl     = (const float*)d_in[5];
    const float* bl     = (const float*)d_in[6];
    const float* Wr     = (const float*)d_in[7];
    const float* br     = (const float*)d_in[8];
    const float* conv_w = (const float*)d_in[9];
    const float* conv_b = (const float*)d_in[10];
    const float* Wskip  = (const float*)d_in[11];
    const float* bskip  = (const float*)d_in[12];
    const float* Wi     = (const float*)d_in[13];
    const float* bi     = (const float*)d_in[14];
    const float* Wf     = (const float*)d_in[15];
    const float* bf_    = (const float*)d_in[16];
    const float* Wo     = (const float*)d_in[17];
    const float* bo     = (const float*)d_in[18];
    const float* Wq     = (const float*)d_in[19];
    const float* bq     = (const float*)d_in[20];
    const float* Wk     = (const float*)d_in[21];
    const float* bk     = (const float*)d_in[22];
    const float* Wv     = (const float*)d_in[23];
    const float* bv     = (const float*)d_in[24];
    const float* Wd     = (const float*)d_in[25];
    const float* bd     = (const float*)d_in[26];
    float* out = (float*)d_out;

    fp16 *xn16, *xt16, *xc16, *cm16;
    fp16 *WlrT, *WsT, *WqT, *WkT, *WvT, *WoT, *WdT;
    float *xt, *r, *skip, *q, *k, *v, *o, *gi, *gf, *aex, *Mex, *bias_lr;
    float *WiT, *WfT;
    cudaGetSymbolAddress((void**)&xn16, g_xn16);
    cudaGetSymbolAddress((void**)&xt,   g_xt);   cudaGetSymbolAddress((void**)&xt16, g_xt16);
    cudaGetSymbolAddress((void**)&xc16, g_xc16);
    cudaGetSymbolAddress((void**)&r,    g_r);    cudaGetSymbolAddress((void**)&skip, g_skip);
    cudaGetSymbolAddress((void**)&q,    g_q);    cudaGetSymbolAddress((void**)&k,    g_k);
    cudaGetSymbolAddress((void**)&v,    g_v);    cudaGetSymbolAddress((void**)&o,    g_o);
    cudaGetSymbolAddress((void**)&gi,   g_ig);   cudaGetSymbolAddress((void**)&gf,   g_fg);
    cudaGetSymbolAddress((void**)&aex,  g_a);    cudaGetSymbolAddress((void**)&Mex,  g_M);
    cudaGetSymbolAddress((void**)&cm16, g_cm16);
    cudaGetSymbolAddress((void**)&WlrT, g_WlrT);
    cudaGetSymbolAddress((void**)&WsT,  g_WsT);  cudaGetSymbolAddress((void**)&WqT,  g_WqT);
    cudaGetSymbolAddress((void**)&WkT,  g_WkT);  cudaGetSymbolAddress((void**)&WvT,  g_WvT);
    cudaGetSymbolAddress((void**)&WoT,  g_WoT);  cudaGetSymbolAddress((void**)&WdT,  g_WdT);
    cudaGetSymbolAddress((void**)&bias_lr, g_bias_lr);
    cudaGetSymbolAddress((void**)&WiT,  g_WiT);  cudaGetSymbolAddress((void**)&WfT,  g_WfT);

    cudaFuncSetAttribute(gemm_mma_kernel,
                         cudaFuncAttributeMaxDynamicSharedMemorySize, GSMEM_BYTES);
    cudaFuncSetAttribute(attn_kernel,
                         cudaFuncAttributeMaxDynamicSharedMemorySize, ASM_BYTES);

    // 1. fused preprocessing: weight transposes + biases/gate-weights + LN
    {
        FusedPrep fp{};
        const float* Ws[8] = { Wl, Wr, Wskip, Wq, Wk, Wv, Wo, Wd };
        fp16* Ts[8] = { WlrT, WlrT + (size_t)PP * DD, WsT, WqT, WkT, WvT, WoT, WdT };
        int Ks[8] = { DD, DD, PP, PP, PP, PP, PP, HD };
        int Ns[8] = { PP, HD, HD, HD, HD, HD, HD, DD };
        int cum = 0;
        for (int i = 0; i < 8; i++) {
            fp.W[i] = Ws[i]; fp.T[i] = Ts[i];
            fp.K[i] = Ks[i]; fp.N[i] = Ns[i];
            fp.cum[i] = cum;
            cum += (Ns[i] / 32) * (Ks[i] / 32);
        }
        fp.cum[8] = cum;
        fp.bl = bl; fp.br = br; fp.Wi = Wi; fp.Wf = Wf;
        fp.x = x; fp.lnw = ln_w; fp.lnb = ln_b; fp.xn16 = xn16;
        fp.miscEnd = cum + 74;
        fused_prep_kernel<<<cum + 74 + NTOK, 256>>>(fp);
    }

    // 2. merged [xt | r] = xn @ [Wl | Wr] + [bl | br]
    {
        GemmParams p{}; p.K = DD; p.scanz = -1;
        p.jobs[0] = { xn16, WlrT, bias_lr, nullptr, xt, xt16, r, PP, PP, HD };
        gemm_mma_kernel<<<dim3(2560/128, NTOK/128, 1), 256, GSMEM_BYTES>>>(p);
    }
    // 3. fused conv + silu + gates
    conv_gates_kernel<<<NTOK, 256>>>(xt, conv_w, conv_b, xc16,
                                     WiT, bi, WfT, bf_, gi, gf);

    // 4. five P->HD projections + gate prefix-scan, one launch
    {
        const int NC = 1 << 30;
        GemmParams p{}; p.K = PP; p.scanz = 5;
        p.gi = gi; p.gf = gf; p.aex = aex; p.Mex = Mex;
        p.jobs[0] = { xc16, WsT, bskip, nullptr, skip, nullptr, nullptr, NC, HD, 0 };
        p.jobs[1] = { xc16, WqT, bq,    nullptr, q,    nullptr, nullptr, NC, HD, 0 };
        p.jobs[2] = { xc16, WkT, bk,    nullptr, k,    nullptr, nullptr, NC, HD, 0 };
        p.jobs[3] = { xt16, WvT, bv,    nullptr, v,    nullptr, nullptr, NC, HD, 0 };
        p.jobs[4] = { xt16, WoT, bo,    nullptr, o,    nullptr, nullptr, NC, HD, 0 };
        gemm_mma_kernel<<<dim3(HD/128, NTOK/128, 6), 256, GSMEM_BYTES>>>(p);
    }

    // 5. parallel attention-form scan -> comb fp16
    attn_kernel<<<dim3(TT/QT, BB*HH), 256, ASM_BYTES>>>(
        q, k, v, aex, Mex, o, skip, r, hln_w, hln_b, cm16);

    // 6. out = comb @ Wd + bd + x
    {
        const int NC = 1 << 30;
        GemmParams p{}; p.K = HD; p.scanz = -1;
        p.jobs[0] = { cm16, WdT, bd, x, out, nullptr, nullptr, NC, DD, 0 };
        gemm_mma_kernel<<<dim3(DD/128, NTOK/128, 1), 256, GSMEM_BYTES>>>(p);
    }
}

// round 17
// speedup vs baseline: 1.4618x; 1.4618x over previous
#include <cuda_runtime.h>
#include <cuda_fp16.h>
#include <cstdint>
#include <math.h>

typedef __half fp16;

// Problem constants
#define BB 4
#define TT 512
#define DD 1024
#define HH 8
#define DH 64
#define HD 512
#define PP 2048
#define NTOK (BB*TT)          // 2048 tokens

// ================= scratch (device globals) =================================
__device__ fp16  g_xn16[NTOK*DD];
__device__ float g_xt  [NTOK*PP];
__device__ fp16  g_xt16[NTOK*PP];
__device__ fp16  g_xc16[NTOK*PP];
__device__ float g_r   [NTOK*HD], g_skip[NTOK*HD];
__device__ float g_o   [NTOK*HD];
__device__ fp16  g_q16 [NTOK*HD], g_k16[NTOK*HD], g_v16T[NTOK*HD];
__device__ float g_ig  [NTOK*HH], g_fg  [NTOK*HH];
__device__ float g_a   [BB*HH*TT], g_M [BB*HH*TT];
__device__ fp16  g_cm16[NTOK*HD];
// transposed weights (fp16): WT[N,K]
__device__ fp16 g_WlrT[2560*DD];      // [Wl | Wr] cols, K=1024
__device__ fp16 g_WsT[HD*PP], g_WqT[HD*PP], g_WkT[HD*PP];
__device__ fp16 g_WvT[HD*PP], g_WoT[HD*PP], g_WdT[DD*HD];
__device__ float g_bias_lr[2560];
__device__ float g_WiT[HH*PP], g_WfT[HH*PP];   // gate weights transposed [H][P]

__device__ __forceinline__ uint32_t smem_u32(const void* p) {
    uint32_t a;
    asm("{ .reg .u64 t; cvta.to.shared.u64 t, %1; cvt.u32.u64 %0, t; }"
        : "=r"(a) : "l"(p));
    return a;
}
__device__ __forceinline__ void cp16(uint32_t s, const void* g) {
    asm volatile("cp.async.cg.shared.global [%0], [%1], 16;" :: "r"(s), "l"(g));
}
__device__ __forceinline__ void ldm4(uint32_t addr, uint32_t* r) {
    asm volatile("ldmatrix.sync.aligned.m8n8.x4.shared.b16 {%0,%1,%2,%3}, [%4];"
                 : "=r"(r[0]), "=r"(r[1]), "=r"(r[2]), "=r"(r[3]) : "r"(addr));
}
__device__ __forceinline__ void mma16816(float* c, const uint32_t* a,
                                         uint32_t b0, uint32_t b1) {
    asm volatile("mma.sync.aligned.m16n8k16.row.col.f32.f16.f16.f32 "
        "{%0,%1,%2,%3}, {%4,%5,%6,%7}, {%8,%9}, {%0,%1,%2,%3};"
        : "+f"(c[0]), "+f"(c[1]), "+f"(c[2]), "+f"(c[3])
        : "r"(a[0]), "r"(a[1]), "r"(a[2]), "r"(a[3]), "r"(b0), "r"(b1));
}
__device__ __forceinline__ uint32_t pack_h2(float x, float y) {
    __half2 t = __floats2half2_rn(x, y);
    return *(uint32_t*)&t;
}

// ============ fused preprocessing: 8 weight transposes + misc + LN =========
struct FusedPrep {
    const float* W[8];
    fp16* T[8];
    int K[8], N[8], cum[9];
    const float *bl, *br, *Wi, *Wf;
    const float *x, *lnw, *lnb;
    fp16* xn16;
    int miscEnd;
};
__global__ __launch_bounds__(256) void fused_prep_kernel(FusedPrep fp)
{
    __shared__ float shmem[32 * 33];
    const int bx = blockIdx.x, tid = threadIdx.x;

    if (bx < fp.cum[8]) {
        int j = 0;
        #pragma unroll
        for (int i = 0; i < 8; i++) if (bx >= fp.cum[i + 1]) j = i + 1;
        const int local = bx - fp.cum[j];
        const int K = fp.K[j], N = fp.N[j];
        const int nbn = N / 32;
        const int n0 = (local % nbn) * 32, k0 = (local / nbn) * 32;
        const float* W = fp.W[j];
        fp16* T = fp.T[j];
        float (*tile)[33] = (float(*)[33])shmem;
        int tx = tid & 31, ty = tid >> 5;
        for (int r = ty; r < 32; r += 8)
            tile[r][tx] = W[(size_t)(k0 + r) * N + n0 + tx];
        __syncthreads();
        for (int r = ty; r < 32; r += 8)
            T[(size_t)(n0 + r) * K + k0 + tx] = __float2half(tile[tx][r]);
    } else if (bx < fp.miscEnd) {
        const int blk = bx - fp.cum[8];
        if (blk < 10) {
            int idx = blk * 256 + tid;
            if (idx < 2560)
                g_bias_lr[idx] = (idx < PP) ? fp.bl[idx] : fp.br[idx - PP];
        } else {
            int idx = (blk - 10) * 256 + tid;
            int h = idx >> 11, p = idx & 2047;
            g_WiT[idx] = fp.Wi[p * HH + h];
            g_WfT[idx] = fp.Wf[p * HH + h];
        }
    } else {
        const int t = bx - fp.miscEnd;
        const float* row = fp.x + (size_t)t * DD;
        float s = 0.f, s2 = 0.f;
        for (int i = tid; i < DD; i += 256) {
            float v = row[i]; s += v; s2 += v * v;
        }
        int warp = tid >> 5, lane = tid & 31;
        #pragma unroll
        for (int o = 16; o; o >>= 1) {
            s  += __shfl_xor_sync(0xffffffffu, s,  o);
            s2 += __shfl_xor_sync(0xffffffffu, s2, o);
        }
        if (lane == 0) { shmem[warp] = s; shmem[8 + warp] = s2; }
        __syncthreads();
        if (tid == 0) {
            float ts = 0.f, ts2 = 0.f;
            #pragma unroll
            for (int i = 0; i < 8; i++) { ts += shmem[i]; ts2 += shmem[8 + i]; }
            float mu  = ts  * (1.f / DD);
            float var = ts2 * (1.f / DD) - mu * mu;
            shmem[0] = mu; shmem[1] = rsqrtf(var + 1e-6f);
        }
        __syncthreads();
        float mu = shmem[0], rstd = shmem[1];
        for (int i = tid; i < DD; i += 256)
            fp.xn16[(size_t)t * DD + i] =
                __float2half((row[i] - mu) * rstd * fp.lnw[i] + fp.lnb[i]);
    }
}

// ============ mma.sync fp16 single-pass GEMM (BK=32, 4-stage) ==============
struct GemmJob {
    const fp16 *A, *B;
    const float *bias, *res;
    float *out;                   // may be null
    fp16 *o16;                    // may be null
    float *out2;                  // columns >= ncut go here (ld = ldo2)
    int ncut, ldo, ldo2;
    float oscale;                 // scale applied to o16 (non-trans)
    int vtrans;                   // o16 stored transposed per (b,h): [d][t]
};
struct GemmParams { GemmJob jobs[5]; int K; };

#define PADK 40
#define OPT  (128*PADK)
#define STG2 (2*OPT)
#define NSTG 4
#define GSMEM_BYTES (NSTG*STG2*2)      // 81920 B -> 2 CTAs/SM

__global__ __launch_bounds__(256, 2) void gemm_mma_kernel(GemmParams p)
{
    const GemmJob J = p.jobs[blockIdx.z];
    const int bm = blockIdx.y * 128, bn = blockIdx.x * 128;

    extern __shared__ fp16 smg[];
    const uint32_t sbase = smem_u32(smg);
    const int K = p.K;
    const int tid = threadIdx.x, lane = tid & 31, wid = tid >> 5;
    const int warpM = wid & 3, warpN = wid >> 2;

    const fp16* gsrc[2];
    gsrc[0] = J.A + (size_t)bm * K;
    gsrc[1] = J.B + (size_t)bn * K;

    const int lrow = tid >> 1;
    const int lcol = (tid & 1) * 16;
    const uint32_t swr = sbase + (uint32_t)(lrow * PADK + lcol) * 2;

    float acc[2][8][4];
    #pragma unroll
    for (int i = 0; i < 2; i++)
        #pragma unroll
        for (int j = 0; j < 8; j++)
            #pragma unroll
            for (int e = 0; e < 4; e++) acc[i][j][e] = 0.f;

    const int NT = K / 32;

    #pragma unroll
    for (int s = 0; s < 3; s++) {
        #pragma unroll
        for (int w = 0; w < 2; w++) {
            const fp16* g = gsrc[w] + (size_t)lrow * K + s * 32 + lcol;
            uint32_t sa = swr + (uint32_t)(s * STG2 + w * OPT) * 2;
            cp16(sa, g); cp16(sa + 16, g + 8);
        }
        asm volatile("cp.async.commit_group;");
    }

    for (int kt = 0; kt < NT; kt++) {
        if (kt < NT - 2)      asm volatile("cp.async.wait_group 2;");
        else if (kt < NT - 1) asm volatile("cp.async.wait_group 1;");
        else                  asm volatile("cp.async.wait_group 0;");
        __syncthreads();

        if (kt + 3 < NT) {
            const int s = (kt + 3) % NSTG;
            const int k0 = (kt + 3) * 32;
            #pragma unroll
            for (int w = 0; w < 2; w++) {
                const fp16* g = gsrc[w] + (size_t)lrow * K + k0 + lcol;
                uint32_t sa = swr + (uint32_t)(s * STG2 + w * OPT) * 2;
                cp16(sa, g); cp16(sa + 16, g + 8);
            }
            asm volatile("cp.async.commit_group;");
        }

        const uint32_t stg = sbase + (uint32_t)((kt % NSTG) * STG2) * 2;
        #pragma unroll
        for (int ks = 0; ks < 2; ks++) {
            const int koff = ks * 16 + ((lane >> 4) << 3);
            const int rsel = lane & 15;
            uint32_t a[2][4], b[4][4];
            #pragma unroll
            for (int i = 0; i < 2; i++) {
                const int row = warpM * 32 + i * 16 + rsel;
                ldm4(stg + (uint32_t)(row * PADK + koff) * 2, a[i]);
            }
            #pragma unroll
            for (int j = 0; j < 4; j++) {
                const int row = warpN * 64 + j * 16 + rsel;
                ldm4(stg + (uint32_t)(OPT + row * PADK + koff) * 2, b[j]);
            }
            #pragma unroll
            for (int i = 0; i < 2; i++)
                #pragma unroll
                for (int j = 0; j < 8; j++)
                    mma16816(acc[i][j], a[i],
                             b[j >> 1][j & 1], b[j >> 1][(j & 1) + 2]);
        }
    }

    const int er = (lane >> 2);
    const int ec = (lane & 3) * 2;
    #pragma unroll
    for (int i = 0; i < 2; i++) {
        #pragma unroll
        for (int j = 0; j < 8; j++) {
            const int row0 = bm + warpM * 32 + i * 16 + er;
            const int col0 = bn + warpN * 64 + j * 8 + ec;
            #pragma unroll
            for (int e = 0; e < 4; e++) {
                const int row = row0 + (e >> 1) * 8;
                const int col = col0 + (e & 1);
                float v = acc[i][j][e] + J.bias[col];
                if (col >= J.ncut) {
                    J.out2[(size_t)row * J.ldo2 + (col - J.ncut)] = v;
                } else {
                    if (J.res) v += J.res[(size_t)row * J.ldo + col];
                    const size_t idx = (size_t)row * J.ldo + col;
                    if (J.out) J.out[idx] = v;
                    if (J.o16) {
                        if (!J.vtrans) {
                            J.o16[idx] = __float2half(v * J.oscale);
                        } else {
                            const int hh_ = col >> 6, dd_ = col & 63;
                            const int bb_ = row >> 9, tt_ = row & (TT - 1);
                            J.o16[(size_t)((bb_ * HH + hh_) * DH + dd_) * TT + tt_]
                                = __float2half(v);
                        }
                    }
                }
            }
        }
    }
}

// ====== fused causal conv + silu + i/f gates (one CTA per token) ===========
__global__ __launch_bounds__(256) void conv_gates_kernel(
    const float* __restrict__ xt, const float* __restrict__ cw,
    const float* __restrict__ cbp, fp16* __restrict__ xc16,
    const float* __restrict__ WiT, const float* __restrict__ bi,
    const float* __restrict__ WfT, const float* __restrict__ bf_,
    float* __restrict__ gi, float* __restrict__ gf)
{
    const int t = blockIdx.x, tid = threadIdx.x;
    __shared__ float row[PP];
    __shared__ float y[PP];

    {
        const float4* src = (const float4*)(xt + (size_t)t * PP);
        float4* rs = (float4*)row;
        rs[tid]       = src[tid];
        rs[tid + 256] = src[tid + 256];
    }
    __syncthreads();

    const float w0 = cw[0], w1 = cw[1], w2 = cw[2], w3 = cw[3], cb = cbp[0];
    #pragma unroll
    for (int i = 0; i < 2; i++) {
        const int p = (tid + 256 * i) * 4;
        float o[4];
        #pragma unroll
        for (int e = 0; e < 4; e++) {
            const int pp = p + e;
            float acc = row[pp] * w3 + cb;
            if (pp >= 1) acc += row[pp - 1] * w2;
            if (pp >= 2) acc += row[pp - 2] * w1;
            if (pp >= 3) acc += row[pp - 3] * w0;
            o[e] = acc / (1.f + __expf(-acc));
        }
        *(float4*)&y[p] = make_float4(o[0], o[1], o[2], o[3]);
        __half2* h2 = (__half2*)(xc16 + (size_t)t * PP + p);
        h2[0] = __floats2half2_rn(o[0], o[1]);
        h2[1] = __floats2half2_rn(o[2], o[3]);
    }
    __syncthreads();

    const int warp = tid >> 5, lane = tid & 31;
    const float* wi = WiT + warp * PP;
    const float* wf = WfT + warp * PP;
    float si = 0.f, sf = 0.f;
    for (int p = lane * 4; p < PP; p += 128) {
        float4 xv = *(const float4*)&y[p];
        float4 a  = *(const float4*)(wi + p);
        float4 b  = *(const float4*)(wf + p);
        si += xv.x*a.x + xv.y*a.y + xv.z*a.z + xv.w*a.w;
        sf += xv.x*b.x + xv.y*b.y + xv.z*b.z + xv.w*b.w;
    }
    #pragma unroll
    for (int o = 16; o; o >>= 1) {
        si += __shfl_xor_sync(0xffffffffu, si, o);
        sf += __shfl_xor_sync(0xffffffffu, sf, o);
    }
    if (lane == 0) {
        float a  = si + bi[warp];
        float b2 = sf + bf_[warp];
        gi[t * HH + warp] = 15.f * tanhf(a  * (1.f / 15.f));
        gf[t * HH + warp] = 15.f * tanhf(b2 * (1.f / 15.f));
    }
}

// ================= gate prefix scans (exact linearization) =================
__global__ __launch_bounds__(TT) void gatescan_kernel(
    const float* __restrict__ gi, const float* __restrict__ gf,
    float* __restrict__ a_out, float* __restrict__ M_out)
{
    const int bh = blockIdx.x;
    const int b = bh >> 3, h = bh & 7;
    const int t = threadIdx.x;
    __shared__ float sf[TT], sa[TT];
    const int gidx = (b * TT + t) * HH + h;
    sf[t] = gf[gidx];
    const float iv = gi[gidx];
    __syncthreads();
    #pragma unroll
    for (int st = 1; st < TT; st <<= 1) {
        float add = (t >= st) ? sf[t - st] : 0.f;
        __syncthreads();
        sf[t] += add;
        __syncthreads();
    }
    const float a = iv - sf[t];
    a_out[bh * TT + t] = a;
    sa[t] = a;
    __syncthreads();
    #pragma unroll
    for (int st = 1; st < TT; st <<= 1) {
        float mx = (t >= st) ? sa[t - st] : -3.4e38f;
        __syncthreads();
        sa[t] = fmaxf(sa[t], mx);
        __syncthreads();
    }
    M_out[bh * TT + t] = fmaxf(0.f, sa[t]);
}

// ================= tensor-core attention-form scan =========================
// CTA: 64 queries of one (b,h); 4 warps, warp w = rows 16w..16w+15.
// S = q @ k^T (fp16 mma), weights fp32, P·V^T (fp16 mma, S-frag -> A-frag).
#define ATP 72   // halves per smem row (64 + 8); row stride 144B (16B-aligned)

__global__ __launch_bounds__(128) void attn_mma_kernel(
    const fp16* __restrict__ q16, const fp16* __restrict__ k16,
    const fp16* __restrict__ v16T,
    const float* __restrict__ aex, const float* __restrict__ Mex,
    const float* __restrict__ oraw, const float* __restrict__ skip,
    const float* __restrict__ rraw,
    const float* __restrict__ hlnw, const float* __restrict__ hlnb,
    fp16* __restrict__ out16)
{
    const int bh = blockIdx.y, b = bh >> 3, h = bh & 7;
    const int t0 = blockIdx.x * 64;
    __shared__ fp16 qs[64 * ATP], ks[64 * ATP], vts[64 * ATP];
    __shared__ float as_[64], Mts[64], sumqs[64];

    const int tid = threadIdx.x, lane = tid & 31, wid = tid >> 5;
    const uint32_t qs_b = smem_u32(qs), ks_b = smem_u32(ks), vts_b = smem_u32(vts);

    // load q tile [64 tok][64 d]
    #pragma unroll
    for (int i = 0; i < 4; i++) {
        const int idx = i * 128 + tid;            // 0..511 int4s
        const int rr = idx >> 3, c4 = idx & 7;
        *(int4*)(qs + rr * ATP + c4 * 8) =
            *(const int4*)(q16 + (size_t)(b * TT + t0 + rr) * HD + h * DH + c4 * 8);
    }
    __syncthreads();
    if (tid < 64) {
        float s = 0.f;
        #pragma unroll 8
        for (int d = 0; d < DH; d++) s += __half2float(qs[tid * ATP + d]);
        sumqs[tid] = s;
        Mts[tid] = Mex[bh * TT + t0 + tid];
    }

    const int rsel = lane & 15, koff = (lane >> 4) << 3;
    const int er = lane >> 2, ec = (lane & 3) * 2;
    const int r0 = wid * 16 + er, r1 = r0 + 8;

    float den0 = 0.f, den1 = 0.f;
    float O[8][4];
    #pragma unroll
    for (int f = 0; f < 8; f++)
        #pragma unroll
        for (int e = 0; e < 4; e++) O[f][e] = 0.f;

    for (int j0 = 0; j0 <= t0; j0 += 64) {
        #pragma unroll
        for (int i = 0; i < 4; i++) {
            const int idx = i * 128 + tid;
            const int rr = idx >> 3, c4 = idx & 7;
            *(int4*)(ks + rr * ATP + c4 * 8) =
                *(const int4*)(k16 + (size_t)(b * TT + j0 + rr) * HD + h * DH + c4 * 8);
            *(int4*)(vts + rr * ATP + c4 * 8) =
                *(const int4*)(v16T + (size_t)(bh * DH + rr) * TT + j0 + c4 * 8);
        }
        if (tid < 64) as_[tid] = aex[bh * TT + j0 + tid];
        __syncthreads();

        // S = q @ k^T
        float S[8][4];
        #pragma unroll
        for (int f = 0; f < 8; f++)
            #pragma unroll
            for (int e = 0; e < 4; e++) S[f][e] = 0.f;
        #pragma unroll
        for (int kk = 0; kk < 4; kk++) {
            uint32_t a[4];
            ldm4(qs_b + (uint32_t)((wid * 16 + rsel) * ATP + kk * 16 + koff) * 2, a);
            #pragma unroll
            for (int g = 0; g < 4; g++) {
                uint32_t bb[4];
                ldm4(ks_b + (uint32_t)((g * 16 + rsel) * ATP + kk * 16 + koff) * 2, bb);
                mma16816(S[2 * g],     a, bb[0], bb[2]);
                mma16816(S[2 * g + 1], a, bb[1], bb[3]);
            }
        }

        // exponent weights (both factors <= 1: a_j <= M_j <= M_row; M nondecr.)
        const float Mt0 = Mts[r0], Mt1 = Mts[r1];
        const float rat = __expf(Mt0 - Mt1);
        const bool diag = (j0 == t0);
        uint32_t Ph[8][2];
        #pragma unroll
        for (int f = 0; f < 8; f++) {
            const int jl = f * 8 + ec;
            const float e0 = __expf(as_[jl]     - Mt0);
            const float e1 = __expf(as_[jl + 1] - Mt0);
            float w00 = e0 * S[f][0], w01 = e1 * S[f][1];
            float w10 = e0 * rat * S[f][2], w11 = e1 * rat * S[f][3];
            if (diag) {
                if (jl     > r0) w00 = 0.f;
                if (jl + 1 > r0) w01 = 0.f;
                if (jl     > r1) w10 = 0.f;
                if (jl + 1 > r1) w11 = 0.f;
            }
            den0 += w00 + w01;
            den1 += w10 + w11;
            Ph[f][0] = pack_h2(w00, w01);
            Ph[f][1] = pack_h2(w10, w11);
        }

        // O += P @ V^T
        #pragma unroll
        for (int g = 0; g < 4; g++) {
            uint32_t ap[4] = { Ph[2*g][0], Ph[2*g][1], Ph[2*g+1][0], Ph[2*g+1][1] };
            #pragma unroll
            for (int gd = 0; gd < 4; gd++) {
                uint32_t bb[4];
                ldm4(vts_b + (uint32_t)((gd * 16 + rsel) * ATP + g * 16 + koff) * 2, bb);
                mma16816(O[2 * gd],     ap, bb[0], bb[2]);
                mma16816(O[2 * gd + 1], ap, bb[1], bb[3]);
            }
        }
        __syncthreads();
    }

    // quad reduction of den (lanes er-equal are lane^1, lane^2)
    den0 += __shfl_xor_sync(0xffffffffu, den0, 1);
    den0 += __shfl_xor_sync(0xffffffffu, den0, 2);
    den1 += __shfl_xor_sync(0xffffffffu, den1, 1);
    den1 += __shfl_xor_sync(0xffffffffu, den1, 2);
    const float Mt0 = Mts[r0], Mt1 = Mts[r1];
    const float rd0 = 1.f / fmaxf(den0 + __expf(-Mt0) * sumqs[r0], 1.f);
    const float rd1 = 1.f / fmaxf(den1 + __expf(-Mt1) * sumqs[r1], 1.f);

    const int tg0 = b * TT + t0 + r0;
    const int tg1 = tg0 + 8;
    float s10 = 0.f, s20 = 0.f, s11 = 0.f, s21 = 0.f;
    #pragma unroll
    for (int f = 0; f < 8; f++) {
        const int d = f * 8 + ec;
        const size_t i00 = (size_t)tg0 * HD + h * DH + d;
        const size_t i10 = (size_t)tg1 * HD + h * DH + d;
        float og;
        og = 1.f / (1.f + __expf(-oraw[i00]));     O[f][0] = og * O[f][0] * rd0;
        og = 1.f / (1.f + __expf(-oraw[i00 + 1])); O[f][1] = og * O[f][1] * rd0;
        og = 1.f / (1.f + __expf(-oraw[i10]));     O[f][2] = og * O[f][2] * rd1;
        og = 1.f / (1.f + __expf(-oraw[i10 + 1])); O[f][3] = og * O[f][3] * rd1;
        s10 += O[f][0] + O[f][1];
        s20 += O[f][0]*O[f][0] + O[f][1]*O[f][1];
        s11 += O[f][2] + O[f][3];
        s21 += O[f][2]*O[f][2] + O[f][3]*O[f][3];
    }
    s10 += __shfl_xor_sync(0xffffffffu, s10, 1);
    s10 += __shfl_xor_sync(0xffffffffu, s10, 2);
    s20 += __shfl_xor_sync(0xffffffffu, s20, 1);
    s20 += __shfl_xor_sync(0xffffffffu, s20, 2);
    s11 += __shfl_xor_sync(0xffffffffu, s11, 1);
    s11 += __shfl_xor_sync(0xffffffffu, s11, 2);
    s21 += __shfl_xor_sync(0xffffffffu, s21, 1);
    s21 += __shfl_xor_sync(0xffffffffu, s21, 2);
    const float mu0 = s10 * (1.f / DH);
    const float vr0 = s20 * (1.f / DH) - mu0 * mu0;
    const float rs0 = rsqrtf(vr0 + 1e-6f);
    const float mu1 = s11 * (1.f / DH);
    const float vr1 = s21 * (1.f / DH) - mu1 * mu1;
    const float rs1 = rsqrtf(vr1 + 1e-6f);

    #pragma unroll
    for (int f = 0; f < 8; f++) {
        const int d = f * 8 + ec;
        #pragma unroll
        for (int e = 0; e < 4; e++) {
            const int dd = d + (e & 1);
            const int tg = (e < 2) ? tg0 : tg1;
            const float mu = (e < 2) ? mu0 : mu1;
            const float rs = (e < 2) ? rs0 : rs1;
            const size_t ix = (size_t)tg * HD + h * DH + dd;
            const float hn = (O[f][e] - mu) * rs * hlnw[h * DH + dd] + hlnb[h * DH + dd];
            const float rv = rraw[ix];
            const float sil = rv / (1.f + __expf(-rv));
            out16[ix] = __float2half((hn + skip[ix]) * sil);
        }
    }
}

// ===========================================================================
extern "C" void kernel_launch(void* const* d_in, const int* in_sizes, int n_in,
                              void* d_out, int out_size)
{
    const float* x      = (const float*)d_in[0];
    const float* ln_w   = (const float*)d_in[1];
    const float* ln_b   = (const float*)d_in[2];
    const float* hln_w  = (const float*)d_in[3];
    const float* hln_b  = (const float*)d_in[4];
    const float* Wl     = (const float*)d_in[5];
    const float* bl     = (const float*)d_in[6];
    const float* Wr     = (const float*)d_in[7];
    const float* br     = (const float*)d_in[8];
    const float* conv_w = (const float*)d_in[9];
    const float* conv_b = (const float*)d_in[10];
    const float* Wskip  = (const float*)d_in[11];
    const float* bskip  = (const float*)d_in[12];
    const float* Wi     = (const float*)d_in[13];
    const float* bi     = (const float*)d_in[14];
    const float* Wf     = (const float*)d_in[15];
    const float* bf_    = (const float*)d_in[16];
    const float* Wo     = (const float*)d_in[17];
    const float* bo     = (const float*)d_in[18];
    const float* Wq     = (const float*)d_in[19];
    const float* bq     = (const float*)d_in[20];
    const float* Wk     = (const float*)d_in[21];
    const float* bk     = (const float*)d_in[22];
    const float* Wv     = (const float*)d_in[23];
    const float* bv     = (const float*)d_in[24];
    const float* Wd     = (const float*)d_in[25];
    const float* bd     = (const float*)d_in[26];
    float* out = (float*)d_out;

    fp16 *xn16, *xt16, *xc16, *cm16, *q16, *k16, *v16T;
    fp16 *WlrT, *WsT, *WqT, *WkT, *WvT, *WoT, *WdT;
    float *xt, *r, *skip, *og, *gi, *gf, *aex, *Mex, *bias_lr;
    float *WiT, *WfT;
    cudaGetSymbolAddress((void**)&xn16, g_xn16);
    cudaGetSymbolAddress((void**)&xt,   g_xt);   cudaGetSymbolAddress((void**)&xt16, g_xt16);
    cudaGetSymbolAddress((void**)&xc16, g_xc16);
    cudaGetSymbolAddress((void**)&r,    g_r);    cudaGetSymbolAddress((void**)&skip, g_skip);
    cudaGetSymbolAddress((void**)&og,   g_o);
    cudaGetSymbolAddress((void**)&q16,  g_q16);  cudaGetSymbolAddress((void**)&k16,  g_k16);
    cudaGetSymbolAddress((void**)&v16T, g_v16T);
    cudaGetSymbolAddress((void**)&gi,   g_ig);   cudaGetSymbolAddress((void**)&gf,   g_fg);
    cudaGetSymbolAddress((void**)&aex,  g_a);    cudaGetSymbolAddress((void**)&Mex,  g_M);
    cudaGetSymbolAddress((void**)&cm16, g_cm16);
    cudaGetSymbolAddress((void**)&WlrT, g_WlrT);
    cudaGetSymbolAddress((void**)&WsT,  g_WsT);  cudaGetSymbolAddress((void**)&WqT,  g_WqT);
    cudaGetSymbolAddress((void**)&WkT,  g_WkT);  cudaGetSymbolAddress((void**)&WvT,  g_WvT);
    cudaGetSymbolAddress((void**)&WoT,  g_WoT);  cudaGetSymbolAddress((void**)&WdT,  g_WdT);
    cudaGetSymbolAddress((void**)&bias_lr, g_bias_lr);
    cudaGetSymbolAddress((void**)&WiT,  g_WiT);  cudaGetSymbolAddress((void**)&WfT,  g_WfT);

    cudaFuncSetAttribute(gemm_mma_kernel,
                         cudaFuncAttributeMaxDynamicSharedMemorySize, GSMEM_BYTES);

    // 1. fused preprocessing
    {
        FusedPrep fp{};
        const float* Ws[8] = { Wl, Wr, Wskip, Wq, Wk, Wv, Wo, Wd };
        fp16* Ts[8] = { WlrT, WlrT + (size_t)PP * DD, WsT, WqT, WkT, WvT, WoT, WdT };
        int Ks[8] = { DD, DD, PP, PP, PP, PP, PP, HD };
        int Ns[8] = { PP, HD, HD, HD, HD, HD, HD, DD };
        int cum = 0;
        for (int i = 0; i < 8; i++) {
            fp.W[i] = Ws[i]; fp.T[i] = Ts[i];
            fp.K[i] = Ks[i]; fp.N[i] = Ns[i];
            fp.cum[i] = cum;
            cum += (Ns[i] / 32) * (Ks[i] / 32);
        }
        fp.cum[8] = cum;
        fp.bl = bl; fp.br = br; fp.Wi = Wi; fp.Wf = Wf;
        fp.x = x; fp.lnw = ln_w; fp.lnb = ln_b; fp.xn16 = xn16;
        fp.miscEnd = cum + 74;
        fused_prep_kernel<<<cum + 74 + NTOK, 256>>>(fp);
    }

    // 2. merged [xt | r] = xn @ [Wl | Wr] + [bl | br]
    {
        GemmParams p{}; p.K = DD;
        p.jobs[0] = { xn16, WlrT, bias_lr, nullptr, xt, xt16, r, PP, PP, HD, 1.f, 0 };
        gemm_mma_kernel<<<dim3(2560/128, NTOK/128, 1), 256, GSMEM_BYTES>>>(p);
    }
    // 3. fused conv + silu + gates
    conv_gates_kernel<<<NTOK, 256>>>(xt, conv_w, conv_b, xc16,
                                     WiT, bi, WfT, bf_, gi, gf);

    // 4. five P->HD projections (q/k/v straight to fp16; k scaled, v transposed)
    {
        const int NC = 1 << 30;
        GemmParams p{}; p.K = PP;
        p.jobs[0] = { xc16, WsT, bskip, nullptr, skip, nullptr, nullptr, NC, HD, 0, 1.f, 0 };
        p.jobs[1] = { xc16, WqT, bq, nullptr, nullptr, q16,  nullptr, NC, HD, 0, 1.f,    0 };
        p.jobs[2] = { xc16, WkT, bk, nullptr, nullptr, k16,  nullptr, NC, HD, 0, 0.125f, 0 };
        p.jobs[3] = { xt16, WvT, bv, nullptr, nullptr, v16T, nullptr, NC, HD, 0, 1.f,    1 };
        p.jobs[4] = { xt16, WoT, bo, nullptr, og, nullptr, nullptr, NC, HD, 0, 1.f, 0 };
        gemm_mma_kernel<<<dim3(HD/128, NTOK/128, 5), 256, GSMEM_BYTES>>>(p);
    }
    // 5. gate prefix scans
    gatescan_kernel<<<BB*HH, TT>>>(gi, gf, aex, Mex);

    // 6. tensor-core attention-form scan -> comb fp16
    attn_mma_kernel<<<dim3(TT/64, BB*HH), 128>>>(
        q16, k16, v16T, aex, Mex, og, skip, r, hln_w, hln_b, cm16);

    // 7. out = comb @ Wd + bd + x
    {
        const int NC = 1 << 30;
        GemmParams p{}; p.K = HD;
        p.jobs[0] = { cm16, WdT, bd, x, out, nullptr, nullptr, NC, DD, 0, 1.f, 0 };
        gemm_mma_kernel<<<dim3(DD/128, NTOK/128, 1), 256, GSMEM_BYTES>>>(p);
    }
}